// round 2
// baseline (speedup 1.0000x reference)
#include <cuda_runtime.h>
#include <math.h>

#define BB 64
#define TT 2048
#define DD 256
#define NN (BB*TT)

// GEMM tiling
#define MT 128   // frames per CTA
#define NT 128   // output dims per chunk
#define KT 32    // K chunk
#define XSS 132  // padded smem row stride (4-way max bank conflict on transpose store)
#define WSS 132

// scratch for per-frame attention scores (device global: no allocations allowed)
__device__ float g_scores[NN];

__device__ __forceinline__ unsigned long long dup_f32(float v) {
    unsigned long long r;
    asm("mov.b64 %0, {%1, %1};" : "=l"(r) : "f"(v));
    return r;
}
__device__ __forceinline__ void fma2(unsigned long long& d, unsigned long long a, unsigned long long b) {
    // packed fp32x2 FMA: d.lo += a.lo*b.lo ; d.hi += a.hi*b.hi   (SASS: FFMA2)
    asm("fma.rn.f32x2 %0, %1, %2, %0;" : "+l"(d) : "l"(a), "l"(b));
}
__device__ __forceinline__ void unpack2(unsigned long long v, float& lo, float& hi) {
    asm("mov.b64 {%0, %1}, %2;" : "=f"(lo), "=f"(hi) : "l"(v));
}

// ---------------------------------------------------------------------------
// Kernel 1: scores[n] = sum_e attn[e] * tanh( b[e] + sum_d W[e,d] * x[n,d] )
// ---------------------------------------------------------------------------
__global__ __launch_bounds__(256, 2)
void score_kernel(const float* __restrict__ x, const float* __restrict__ W,
                  const float* __restrict__ bias, const float* __restrict__ attn)
{
    __shared__ float Xs[KT][XSS];   // k-major frame tile
    __shared__ float Ws[KT][WSS];   // k-major weight tile

    const int tid = threadIdx.x;
    const int tx  = tid & 15;       // e-group  (8 e's each)
    const int ty  = tid >> 4;       // frame-group (8 frames each)
    const long m0 = (long)blockIdx.x * MT;

    const int lm = tid >> 3;        // load row  (0..31)
    const int lc = (tid & 7) * 4;   // load col  (0..28)

    float sc[8];                    // per-frame score partials (this thread's e's)
#pragma unroll
    for (int i = 0; i < 8; i++) sc[i] = 0.f;

#pragma unroll 1
    for (int ec = 0; ec < DD / NT; ec++) {
        unsigned long long acc[4][8];   // [frame-pair][e] packed f32x2 accumulators
#pragma unroll
        for (int p = 0; p < 4; p++)
#pragma unroll
            for (int j = 0; j < 8; j++) acc[p][j] = 0ull;

#pragma unroll 1
        for (int k0 = 0; k0 < DD; k0 += KT) {
            __syncthreads();
            // load X tile (transpose to k-major)
#pragma unroll
            for (int r = 0; r < 4; r++) {
                int m = lm + r * 32;
                float4 v = *(const float4*)&x[(m0 + m) * DD + k0 + lc];
                Xs[lc+0][m] = v.x; Xs[lc+1][m] = v.y; Xs[lc+2][m] = v.z; Xs[lc+3][m] = v.w;
            }
            // load W tile (transpose to k-major)
#pragma unroll
            for (int r = 0; r < 4; r++) {
                int e = lm + r * 32;
                float4 v = *(const float4*)&W[(ec * NT + e) * DD + k0 + lc];
                Ws[lc+0][e] = v.x; Ws[lc+1][e] = v.y; Ws[lc+2][e] = v.z; Ws[lc+3][e] = v.w;
            }
            __syncthreads();

#pragma unroll
            for (int kk = 0; kk < KT; kk++) {
                // 8 frames of this thread: 4 packed pairs, loaded as 2x LDS.128
                const ulonglong2* au = (const ulonglong2*)&Xs[kk][ty * 8];
                ulonglong2 aA = au[0], aB = au[1];
                unsigned long long a2[4] = {aA.x, aA.y, aB.x, aB.y};
                // 8 e-values of this thread, each duplicated into both lanes
                const float4* bp = (const float4*)&Ws[kk][tx * 8];
                float4 b0 = bp[0], b1 = bp[1];
                unsigned long long bd[8];
                bd[0]=dup_f32(b0.x); bd[1]=dup_f32(b0.y); bd[2]=dup_f32(b0.z); bd[3]=dup_f32(b0.w);
                bd[4]=dup_f32(b1.x); bd[5]=dup_f32(b1.y); bd[6]=dup_f32(b1.z); bd[7]=dup_f32(b1.w);
#pragma unroll
                for (int j = 0; j < 8; j++)
#pragma unroll
                    for (int p = 0; p < 4; p++)
                        fma2(acc[p][j], a2[p], bd[j]);
            }
        }

        // epilogue: bias + tanh + attn weighting, fold into per-frame partials
#pragma unroll
        for (int j = 0; j < 8; j++) {
            int e = ec * NT + tx * 8 + j;
            float be = bias[e];
            float ae = attn[e];
#pragma unroll
            for (int p = 0; p < 4; p++) {
                float lo, hi;
                unpack2(acc[p][j], lo, hi);
                sc[2*p]   += ae * tanhf(lo + be);
                sc[2*p+1] += ae * tanhf(hi + be);
            }
        }
    }

    // reduce across the 16 e-lanes (tx = lane bits 0..3, same half-warp)
#pragma unroll
    for (int off = 8; off >= 1; off >>= 1)
#pragma unroll
        for (int i = 0; i < 8; i++)
            sc[i] += __shfl_xor_sync(0xffffffffu, sc[i], off);

    if (tx == 0) {
#pragma unroll
        for (int i = 0; i < 8; i++)
            g_scores[m0 + ty * 8 + i] = sc[i];
    }
}

// ---------------------------------------------------------------------------
// Kernel 2: masked softmax over T, then mu / sqrt(var) per dim.
// grid = (B, 4); each CTA handles a 64-dim slice of one batch row.
// ---------------------------------------------------------------------------
__global__ __launch_bounds__(256)
void pool_kernel(const float* __restrict__ x, const int* __restrict__ mask,
                 float* __restrict__ out)
{
    __shared__ float p[TT];       // unnormalized softmax weights
    __shared__ float rbuf[256];
    const int b   = blockIdx.x;
    const int gy  = blockIdx.y;
    const int tid = threadIdx.x;
    const float* sb = g_scores + b * TT;
    const int*   mb = mask + b * TT;

    // 1) masked max
    float mx = -3.4e38f;
    for (int t = tid; t < TT; t += 256)
        if (mb[t]) mx = fmaxf(mx, sb[t]);
    rbuf[tid] = mx;
    __syncthreads();
    for (int s = 128; s > 0; s >>= 1) {
        if (tid < s) rbuf[tid] = fmaxf(rbuf[tid], rbuf[tid + s]);
        __syncthreads();
    }
    mx = rbuf[0];
    __syncthreads();

    // 2) exp weights + sum
    float sum = 0.f;
    for (int t = tid; t < TT; t += 256) {
        float v = mb[t] ? __expf(sb[t] - mx) : 0.f;
        p[t] = v;
        sum += v;
    }
    rbuf[tid] = sum;
    __syncthreads();
    for (int s = 128; s > 0; s >>= 1) {
        if (tid < s) rbuf[tid] += rbuf[tid + s];
        __syncthreads();
    }
    const float inv = 1.f / rbuf[0];
    __syncthreads();

    // 3) weighted stats: thread (dl, tg) covers dim gy*64+dl over t = tg::4
    const int dl = tid & 63;
    const int tg = tid >> 6;
    const int d  = gy * 64 + dl;
    const float* xb = x + ((long)b * TT) * DD + d;
    float mu = 0.f, m2 = 0.f;
#pragma unroll 4
    for (int t = tg; t < TT; t += 4) {
        float w = p[t];
        float v = xb[(long)t * DD];
        mu += w * v;
        m2 += w * v * v;
    }
    rbuf[tid] = mu;
    __syncthreads();
    float muf = 0.f;
    if (tg == 0) muf = rbuf[dl] + rbuf[64+dl] + rbuf[128+dl] + rbuf[192+dl];
    __syncthreads();
    rbuf[tid] = m2;
    __syncthreads();
    if (tg == 0) {
        float m2f = rbuf[dl] + rbuf[64+dl] + rbuf[128+dl] + rbuf[192+dl];
        muf *= inv; m2f *= inv;
        float var = fmaxf(m2f - muf * muf, 1e-5f);
        out[b * 2 * DD + d]      = muf;
        out[b * 2 * DD + DD + d] = sqrtf(var);
    }
}

// ---------------------------------------------------------------------------
extern "C" void kernel_launch(void* const* d_in, const int* in_sizes, int n_in,
                              void* d_out, int out_size)
{
    const float* xs   = (const float*)d_in[0];
    const int*   mask = (const int*)  d_in[1];
    // d_in[2] = mask2 (unused by the module)
    const float* W    = (const float*)d_in[3];
    const float* bias = (const float*)d_in[4];
    const float* attn = (const float*)d_in[5];
    float* out = (float*)d_out;

    score_kernel<<<NN / MT, 256>>>(xs, W, bias, attn);
    pool_kernel<<<dim3(BB, 4), 256>>>(xs, mask, out);
}

// round 3
// speedup vs baseline: 1.1309x; 1.1309x over previous
#include <cuda_runtime.h>
#include <math.h>

#define BB 64
#define TT 2048
#define DD 256
#define NN (BB*TT)

// GEMM tiling
#define MT 128   // frames per CTA
#define NT 128   // output dims per chunk
#define KT 32    // K chunk
#define XSS 132  // padded smem row stride
#define WSS 132

// device scratch (no allocations allowed)
__device__ float g_scores[NN];
__device__ float g_w[NN];
__device__ float g_part[BB * 8 * 2 * DD];

__device__ __forceinline__ unsigned long long dup_f32(float v) {
    unsigned long long r;
    asm("mov.b64 %0, {%1, %1};" : "=l"(r) : "f"(v));
    return r;
}
__device__ __forceinline__ void fma2(unsigned long long& d, unsigned long long a, unsigned long long b) {
    // packed fp32x2 FMA (SASS: FFMA2): d.lo += a.lo*b.lo ; d.hi += a.hi*b.hi
    asm("fma.rn.f32x2 %0, %1, %2, %0;" : "+l"(d) : "l"(a), "l"(b));
}
__device__ __forceinline__ void unpack2(unsigned long long v, float& lo, float& hi) {
    asm("mov.b64 {%0, %1}, %2;" : "=f"(lo), "=f"(hi) : "l"(v));
}

// ---------------------------------------------------------------------------
// Kernel 1: scores[n] = sum_e attn[e] * tanh( b[e] + sum_d W[e,d] * x[n,d] )
// Frames packed in f32x2 pairs; e's owned STRIDED (tx + 16j) so b-fragment
// scalar LDS.32 reads are bank-conflict-free (16 consecutive floats/half-warp).
// ---------------------------------------------------------------------------
__global__ __launch_bounds__(256, 2)
void score_kernel(const float* __restrict__ x, const float* __restrict__ W,
                  const float* __restrict__ bias, const float* __restrict__ attn)
{
    __shared__ float Xs[KT][XSS];   // k-major frame tile
    __shared__ float Ws[KT][WSS];   // k-major weight tile

    const int tid = threadIdx.x;
    const int tx  = tid & 15;       // e-lane (owns e = tx + 16j)
    const int ty  = tid >> 4;       // frame-group (8 frames each)
    const long m0 = (long)blockIdx.x * MT;

    const int lm = tid >> 3;        // load row  (0..31)
    const int lc = (tid & 7) * 4;   // load col  (0..28)

    float sc[8];
#pragma unroll
    for (int i = 0; i < 8; i++) sc[i] = 0.f;

#pragma unroll 1
    for (int ec = 0; ec < DD / NT; ec++) {
        unsigned long long acc[4][8];   // [frame-pair][e] packed f32x2
#pragma unroll
        for (int p = 0; p < 4; p++)
#pragma unroll
            for (int j = 0; j < 8; j++) acc[p][j] = 0ull;

#pragma unroll 1
        for (int k0 = 0; k0 < DD; k0 += KT) {
            __syncthreads();
#pragma unroll
            for (int r = 0; r < 4; r++) {
                int m = lm + r * 32;
                float4 v = *(const float4*)&x[(m0 + m) * DD + k0 + lc];
                Xs[lc+0][m] = v.x; Xs[lc+1][m] = v.y; Xs[lc+2][m] = v.z; Xs[lc+3][m] = v.w;
            }
#pragma unroll
            for (int r = 0; r < 4; r++) {
                int e = lm + r * 32;
                float4 v = *(const float4*)&W[(ec * NT + e) * DD + k0 + lc];
                Ws[lc+0][e] = v.x; Ws[lc+1][e] = v.y; Ws[lc+2][e] = v.z; Ws[lc+3][e] = v.w;
            }
            __syncthreads();

#pragma unroll
            for (int kk = 0; kk < KT; kk++) {
                // 8 frames: 4 packed f32x2 pairs via 2x LDS.128 (broadcast, conflict-free)
                const ulonglong2* au = (const ulonglong2*)&Xs[kk][ty * 8];
                ulonglong2 aA = au[0], aB = au[1];
                unsigned long long a2[4] = {aA.x, aA.y, aB.x, aB.y};
                // 8 strided e-values: scalar LDS.32, conflict-free
                unsigned long long bd[8];
#pragma unroll
                for (int j = 0; j < 8; j++)
                    bd[j] = dup_f32(Ws[kk][tx + 16 * j]);
#pragma unroll
                for (int j = 0; j < 8; j++)
#pragma unroll
                    for (int p = 0; p < 4; p++)
                        fma2(acc[p][j], a2[p], bd[j]);
            }
        }

#pragma unroll
        for (int j = 0; j < 8; j++) {
            int e = ec * NT + tx + 16 * j;
            float be = bias[e];
            float ae = attn[e];
#pragma unroll
            for (int p = 0; p < 4; p++) {
                float lo, hi;
                unpack2(acc[p][j], lo, hi);
                sc[2*p]   += ae * tanhf(lo + be);
                sc[2*p+1] += ae * tanhf(hi + be);
            }
        }
    }

    // reduce across the 16 e-lanes (tx = lane bits 0..3)
#pragma unroll
    for (int off = 8; off >= 1; off >>= 1)
#pragma unroll
        for (int i = 0; i < 8; i++)
            sc[i] += __shfl_xor_sync(0xffffffffu, sc[i], off);

    if (tx == 0) {
#pragma unroll
        for (int i = 0; i < 8; i++)
            g_scores[m0 + ty * 8 + i] = sc[i];
    }
}

// ---------------------------------------------------------------------------
// Kernel 2: masked softmax over T -> normalized weights g_w[b][t]
// ---------------------------------------------------------------------------
__global__ __launch_bounds__(256)
void weights_kernel(const int* __restrict__ mask)
{
    __shared__ float p[TT];
    __shared__ float rbuf[256];
    const int b   = blockIdx.x;
    const int tid = threadIdx.x;
    const float* sb = g_scores + b * TT;
    const int*   mb = mask + b * TT;

    float mx = -3.4e38f;
    for (int t = tid; t < TT; t += 256)
        if (mb[t]) mx = fmaxf(mx, sb[t]);
    rbuf[tid] = mx;
    __syncthreads();
    for (int s = 128; s > 0; s >>= 1) {
        if (tid < s) rbuf[tid] = fmaxf(rbuf[tid], rbuf[tid + s]);
        __syncthreads();
    }
    mx = rbuf[0];
    __syncthreads();

    float sum = 0.f;
    for (int t = tid; t < TT; t += 256) {
        float v = mb[t] ? __expf(sb[t] - mx) : 0.f;
        p[t] = v;
        sum += v;
    }
    rbuf[tid] = sum;
    __syncthreads();
    for (int s = 128; s > 0; s >>= 1) {
        if (tid < s) rbuf[tid] += rbuf[tid + s];
        __syncthreads();
    }
    const float inv = 1.f / rbuf[0];
    __syncthreads();

    for (int t = tid; t < TT; t += 256)
        g_w[b * TT + t] = p[t] * inv;
}

// ---------------------------------------------------------------------------
// Kernel 3: partial weighted stats. grid (B, 8): CTA covers 256 frames,
// thread d accumulates over its 256-frame chunk. Fully coalesced, MLP=8.
// ---------------------------------------------------------------------------
__global__ __launch_bounds__(256)
void stats_kernel(const float* __restrict__ x)
{
    __shared__ float ws[256];
    const int b  = blockIdx.x;
    const int tc = blockIdx.y;
    const int d  = threadIdx.x;

    ws[d] = g_w[b * TT + tc * 256 + d];
    __syncthreads();

    const float* xb = x + ((long)b * TT + tc * 256) * DD + d;
    float mu = 0.f, m2 = 0.f;
#pragma unroll 8
    for (int t = 0; t < 256; t++) {
        float w = ws[t];
        float v = xb[(long)t * DD];
        mu += w * v;
        m2 += w * v * v;
    }
    g_part[((b * 8 + tc) * 2) * DD + d]      = mu;
    g_part[((b * 8 + tc) * 2 + 1) * DD + d]  = m2;
}

// ---------------------------------------------------------------------------
// Kernel 4: finalize — reduce 8 partials, var, sqrt, write out.
// ---------------------------------------------------------------------------
__global__ __launch_bounds__(256)
void finalize_kernel(float* __restrict__ out)
{
    const int b = blockIdx.x;
    const int d = threadIdx.x;
    float mu = 0.f, m2 = 0.f;
#pragma unroll
    for (int tc = 0; tc < 8; tc++) {
        mu += g_part[((b * 8 + tc) * 2) * DD + d];
        m2 += g_part[((b * 8 + tc) * 2 + 1) * DD + d];
    }
    float var = fmaxf(m2 - mu * mu, 1e-5f);
    out[b * 2 * DD + d]      = mu;
    out[b * 2 * DD + DD + d] = sqrtf(var);
}

// ---------------------------------------------------------------------------
extern "C" void kernel_launch(void* const* d_in, const int* in_sizes, int n_in,
                              void* d_out, int out_size)
{
    const float* xs   = (const float*)d_in[0];
    const int*   mask = (const int*)  d_in[1];
    // d_in[2] = mask2 (unused)
    const float* W    = (const float*)d_in[3];
    const float* bias = (const float*)d_in[4];
    const float* attn = (const float*)d_in[5];
    float* out = (float*)d_out;

    score_kernel<<<NN / MT, 256>>>(xs, W, bias, attn);
    weights_kernel<<<BB, 256>>>(mask);
    stats_kernel<<<dim3(BB, 8), 256>>>(xs);
    finalize_kernel<<<BB, 256>>>(out);
}

// round 5
// speedup vs baseline: 2.5634x; 2.2668x over previous
#include <cuda_runtime.h>
#include <cuda_bf16.h>
#include <math.h>
#include <stdint.h>

#define BB 64
#define TT 2048
#define DD 256
#define NN (BB*TT)

#define MT 128                 // frames per CTA
#define KC 32                  // K chunk (bf16)
#define NCH (DD/KC)            // 8 chunks

// ---------------- device scratch (no allocations allowed) ------------------
__device__ float g_scores[NN];
__device__ float g_w[NN];
__device__ float g_part[BB * 8 * 2 * DD];
__device__ __align__(16) __nv_bfloat16 g_Whi[DD * DD];
__device__ __align__(16) __nv_bfloat16 g_Wlo[DD * DD];

// ---------------- smem layout (dynamic), bytes -----------------------------
#define SM_BIAS   0
#define SM_ATTN   1024
#define SM_RED    2048          // 4 x 128 floats
#define SM_TILES  4096
#define A_STRIDE  80            // 32 bf16 padded to 40 (80B): stride/16 odd -> ldmatrix conflict-free
#define OFF_AHI   0             // 128 x 80B = 10240
#define OFF_ALO   10240
#define OFF_BHI   20480         // 256 x 80B = 20480
#define OFF_BLO   40960
#define STG       61440
#define SMEM_BYTES (SM_TILES + 2*STG)   // 126976

// ---------------- PTX helpers (baseline ISA only: sm_80-class) -------------
__device__ __forceinline__ uint32_t smem_u32(const void* p) {
    uint32_t a;
    asm("{ .reg .u64 t; cvta.to.shared.u64 t, %1; cvt.u32.u64 %0, t; }" : "=r"(a) : "l"(p));
    return a;
}
__device__ __forceinline__ void ldsm4(uint32_t* r, uint32_t addr) {
    asm volatile("ldmatrix.sync.aligned.m8n8.x4.shared.b16 {%0,%1,%2,%3}, [%4];"
                 : "=r"(r[0]), "=r"(r[1]), "=r"(r[2]), "=r"(r[3]) : "r"(addr));
}
__device__ __forceinline__ void mma_bf16(float* d, const uint32_t* a, const uint32_t* b) {
    asm volatile("mma.sync.aligned.m16n8k16.row.col.f32.bf16.bf16.f32 "
                 "{%0,%1,%2,%3}, {%4,%5,%6,%7}, {%8,%9}, {%0,%1,%2,%3};"
                 : "+f"(d[0]), "+f"(d[1]), "+f"(d[2]), "+f"(d[3])
                 : "r"(a[0]), "r"(a[1]), "r"(a[2]), "r"(a[3]), "r"(b[0]), "r"(b[1]));
}
#define CP16(dst, src) asm volatile("cp.async.cg.shared.global [%0], [%1], 16;" :: "r"(dst), "l"(src))
#define CP_COMMIT()    asm volatile("cp.async.commit_group;" ::: "memory")
#define CP_WAIT0()     asm volatile("cp.async.wait_group 0;" ::: "memory")

__device__ __forceinline__ uint32_t pk2(float a, float b) {
    __nv_bfloat162 h = __floats2bfloat162_rn(a, b);
    return *(uint32_t*)&h;
}

// ---------------------------------------------------------------------------
// Kernel 0: split W into bf16 hi/lo once.
// ---------------------------------------------------------------------------
__global__ void prep_kernel(const float* __restrict__ W)
{
    int i = blockIdx.x * blockDim.x + threadIdx.x;
    if (i < DD * DD) {
        float w = W[i];
        __nv_bfloat16 h = __float2bfloat16(w);
        g_Whi[i] = h;
        g_Wlo[i] = __float2bfloat16(w - __bfloat162float(h));
    }
}

// ---------------------------------------------------------------------------
// Kernel 1: split-bf16 GEMM on mma.sync (HMMA) + fused tanh/attn epilogue.
// z = X W^T via Ah*Bh + Ah*Bl + Al*Bh, fp32 accum. 512 thr, 16 warps (4Mx4N).
// ---------------------------------------------------------------------------
__global__ __launch_bounds__(512, 1)
void score_kernel(const float* __restrict__ x,
                  const float* __restrict__ bias, const float* __restrict__ attn)
{
    extern __shared__ char smem[];
    const uint32_t sb = smem_u32(smem);
    const int tid = threadIdx.x;
    const int lane = tid & 31;
    const int wid = tid >> 5;
    const int wm = wid & 3;          // M quarter (32 rows)
    const int wn = wid >> 2;         // N quarter (64 cols)
    const long m0 = (long)blockIdx.x * MT;

    if (tid < 256) {
        ((float*)(smem + SM_BIAS))[tid] = bias[tid];
        ((float*)(smem + SM_ATTN))[tid] = attn[tid];
    }

    // ---- A global-load / smem-store helpers ----
    const int ar  = tid >> 3;        // row 0..63 (and +64)
    const int ag  = tid & 7;         // float4 group
    auto ldA = [&](int c, float4& v0, float4& v1) {
        const float* p = &x[(m0 + ar) * DD + c * KC + ag * 4];
        v0 = *(const float4*)p;
        v1 = *(const float4*)(p + 64 * DD);
    };
    auto stA = [&](float4 v0, float4 v1, int s) {
        char* stg = smem + SM_TILES + s * STG;
        uint32_t o = (uint32_t)(ar * A_STRIDE + ag * 8);
        // hi
        uint2 h0, h1, l0, l1;
        __nv_bfloat16 a, b2;
        a = __float2bfloat16(v0.x); b2 = __float2bfloat16(v0.y);
        h0.x = pk2(__bfloat162float(a), __bfloat162float(b2));
        l0.x = pk2(v0.x - __bfloat162float(a), v0.y - __bfloat162float(b2));
        a = __float2bfloat16(v0.z); b2 = __float2bfloat16(v0.w);
        h0.y = pk2(__bfloat162float(a), __bfloat162float(b2));
        l0.y = pk2(v0.z - __bfloat162float(a), v0.w - __bfloat162float(b2));
        a = __float2bfloat16(v1.x); b2 = __float2bfloat16(v1.y);
        h1.x = pk2(__bfloat162float(a), __bfloat162float(b2));
        l1.x = pk2(v1.x - __bfloat162float(a), v1.y - __bfloat162float(b2));
        a = __float2bfloat16(v1.z); b2 = __float2bfloat16(v1.w);
        h1.y = pk2(__bfloat162float(a), __bfloat162float(b2));
        l1.y = pk2(v1.z - __bfloat162float(a), v1.w - __bfloat162float(b2));
        *(uint2*)(stg + OFF_AHI + o)                   = h0;
        *(uint2*)(stg + OFF_AHI + o + 64 * A_STRIDE)   = h1;
        *(uint2*)(stg + OFF_ALO + o)                   = l0;
        *(uint2*)(stg + OFF_ALO + o + 64 * A_STRIDE)   = l1;
    };
    // ---- B cp.async ----
    const int br = tid >> 2;         // row 0..127 (and +128)
    const int bg = tid & 3;          // 16B group
    auto ldB = [&](int c, int s) {
        uint32_t base = sb + SM_TILES + s * STG;
        uint32_t d0 = base + (uint32_t)(br * A_STRIDE + bg * 16);
        uint32_t d1 = d0 + 128 * A_STRIDE;
        const __nv_bfloat16* s0 = &g_Whi[br * DD + c * KC + bg * 8];
        const __nv_bfloat16* l0p = &g_Wlo[br * DD + c * KC + bg * 8];
        CP16(d0 + OFF_BHI, s0);
        CP16(d1 + OFF_BHI, s0 + 128 * DD);
        CP16(d0 + OFF_BLO, l0p);
        CP16(d1 + OFF_BLO, l0p + 128 * DD);
    };

    float acc[2][8][4];
#pragma unroll
    for (int mt = 0; mt < 2; mt++)
#pragma unroll
        for (int nt = 0; nt < 8; nt++)
#pragma unroll
            for (int i = 0; i < 4; i++) acc[mt][nt][i] = 0.f;

    // fragment smem addresses (stage-relative offsets added later)
    const uint32_t a_off = (uint32_t)((wm * 32 + (lane & 15)) * A_STRIDE + (lane >> 4) * 16);
    const uint32_t b_off = (uint32_t)((wn * 64 + (lane & 7) + ((lane >> 4) & 1) * 8) * A_STRIDE
                                      + ((lane >> 3) & 1) * 16);

    // ---- prologue ----
    float4 va0, va1;
    ldA(0, va0, va1);
    ldB(0, 0); CP_COMMIT();
    stA(va0, va1, 0);
    CP_WAIT0();
    __syncthreads();

#pragma unroll 1
    for (int c = 0; c < NCH; c++) {
        const int s = c & 1;
        const bool more = (c + 1) < NCH;
        if (more) { ldA(c + 1, va0, va1); ldB(c + 1, s ^ 1); CP_COMMIT(); }

        const uint32_t stg = sb + SM_TILES + s * STG;
#pragma unroll
        for (int ks = 0; ks < 2; ks++) {
            uint32_t ah[2][4], al[2][4];
#pragma unroll
            for (int mt = 0; mt < 2; mt++) {
                uint32_t ao = stg + a_off + mt * 16 * A_STRIDE + ks * 32;
                ldsm4(ah[mt], ao + OFF_AHI);
                ldsm4(al[mt], ao + OFF_ALO);
            }
#pragma unroll
            for (int p = 0; p < 4; p++) {
                uint32_t bh[4], bl[4];
                uint32_t bo = stg + b_off + p * 16 * A_STRIDE + ks * 32;
                ldsm4(bh, bo + OFF_BHI);
                ldsm4(bl, bo + OFF_BLO);
#pragma unroll
                for (int mt = 0; mt < 2; mt++) {
                    mma_bf16(acc[mt][2*p],   ah[mt], bh);
                    mma_bf16(acc[mt][2*p],   ah[mt], bl);
                    mma_bf16(acc[mt][2*p],   al[mt], bh);
                    mma_bf16(acc[mt][2*p+1], ah[mt], bh + 2);
                    mma_bf16(acc[mt][2*p+1], ah[mt], bl + 2);
                    mma_bf16(acc[mt][2*p+1], al[mt], bh + 2);
                }
            }
        }
        if (more) { stA(va0, va1, s ^ 1); CP_WAIT0(); __syncthreads(); }
    }

    // ---- fused epilogue: attn * tanh(z + bias), reduce over e ----
    const float* bsm = (const float*)(smem + SM_BIAS);
    const float* atm = (const float*)(smem + SM_ATTN);
    float sc[4] = {0.f, 0.f, 0.f, 0.f};
#pragma unroll
    for (int mt = 0; mt < 2; mt++)
#pragma unroll
        for (int nt = 0; nt < 8; nt++) {
            int e0 = wn * 64 + nt * 8 + 2 * (lane & 3);
            float b0 = bsm[e0], b1 = bsm[e0 + 1];
            float a0 = atm[e0], a1 = atm[e0 + 1];
            sc[mt*2+0] += a0 * tanhf(acc[mt][nt][0] + b0) + a1 * tanhf(acc[mt][nt][1] + b1);
            sc[mt*2+1] += a0 * tanhf(acc[mt][nt][2] + b0) + a1 * tanhf(acc[mt][nt][3] + b1);
        }
#pragma unroll
    for (int off = 1; off <= 2; off <<= 1)
#pragma unroll
        for (int i = 0; i < 4; i++)
            sc[i] += __shfl_xor_sync(0xffffffffu, sc[i], off);

    float* red = (float*)(smem + SM_RED);
    if ((lane & 3) == 0) {
        int r = wm * 32 + (lane >> 2);
        red[wn * 128 + r + 0]  = sc[0];   // mt0, +0
        red[wn * 128 + r + 8]  = sc[1];   // mt0, +8
        red[wn * 128 + r + 16] = sc[2];   // mt1, +0
        red[wn * 128 + r + 24] = sc[3];   // mt1, +8
    }
    __syncthreads();
    if (tid < 128)
        g_scores[m0 + tid] = red[tid] + red[128 + tid] + red[256 + tid] + red[384 + tid];
}

// ---------------------------------------------------------------------------
// Kernel 2: masked softmax over T -> normalized weights g_w[b][t]
// ---------------------------------------------------------------------------
__global__ __launch_bounds__(256)
void weights_kernel(const int* __restrict__ mask)
{
    __shared__ float p[TT];
    __shared__ float rbuf[256];
    const int b   = blockIdx.x;
    const int tid = threadIdx.x;
    const float* sbv = g_scores + b * TT;
    const int*   mb  = mask + b * TT;

    float mx = -3.4e38f;
    for (int t = tid; t < TT; t += 256)
        if (mb[t]) mx = fmaxf(mx, sbv[t]);
    rbuf[tid] = mx;
    __syncthreads();
    for (int s = 128; s > 0; s >>= 1) {
        if (tid < s) rbuf[tid] = fmaxf(rbuf[tid], rbuf[tid + s]);
        __syncthreads();
    }
    mx = rbuf[0];
    __syncthreads();

    float sum = 0.f;
    for (int t = tid; t < TT; t += 256) {
        float v = mb[t] ? __expf(sbv[t] - mx) : 0.f;
        p[t] = v;
        sum += v;
    }
    rbuf[tid] = sum;
    __syncthreads();
    for (int s = 128; s > 0; s >>= 1) {
        if (tid < s) rbuf[tid] += rbuf[tid + s];
        __syncthreads();
    }
    const float inv = 1.f / rbuf[0];
    __syncthreads();

    for (int t = tid; t < TT; t += 256)
        g_w[b * TT + t] = p[t] * inv;
}

// ---------------------------------------------------------------------------
// Kernel 3: partial weighted stats. grid (B, 8).
// ---------------------------------------------------------------------------
__global__ __launch_bounds__(256)
void stats_kernel(const float* __restrict__ x)
{
    __shared__ float ws[256];
    const int b  = blockIdx.x;
    const int tc = blockIdx.y;
    const int d  = threadIdx.x;

    ws[d] = g_w[b * TT + tc * 256 + d];
    __syncthreads();

    const float* xb = x + ((long)b * TT + tc * 256) * DD + d;
    float mu = 0.f, m2 = 0.f;
#pragma unroll 8
    for (int t = 0; t < 256; t++) {
        float w = ws[t];
        float v = xb[(long)t * DD];
        mu += w * v;
        m2 += w * v * v;
    }
    g_part[((b * 8 + tc) * 2) * DD + d]     = mu;
    g_part[((b * 8 + tc) * 2 + 1) * DD + d] = m2;
}

// ---------------------------------------------------------------------------
// Kernel 4: finalize
// ---------------------------------------------------------------------------
__global__ __launch_bounds__(256)
void finalize_kernel(float* __restrict__ out)
{
    const int b = blockIdx.x;
    const int d = threadIdx.x;
    float mu = 0.f, m2 = 0.f;
#pragma unroll
    for (int tc = 0; tc < 8; tc++) {
        mu += g_part[((b * 8 + tc) * 2) * DD + d];
        m2 += g_part[((b * 8 + tc) * 2 + 1) * DD + d];
    }
    float var = fmaxf(m2 - mu * mu, 1e-5f);
    out[b * 2 * DD + d]      = mu;
    out[b * 2 * DD + DD + d] = sqrtf(var);
}

// ---------------------------------------------------------------------------
extern "C" void kernel_launch(void* const* d_in, const int* in_sizes, int n_in,
                              void* d_out, int out_size)
{
    const float* xs   = (const float*)d_in[0];
    const int*   mask = (const int*)  d_in[1];
    // d_in[2] = mask2 (unused)
    const float* W    = (const float*)d_in[3];
    const float* bias = (const float*)d_in[4];
    const float* attn = (const float*)d_in[5];
    float* out = (float*)d_out;

    static int smem_set = 0;
    if (!smem_set) {
        cudaFuncSetAttribute(score_kernel, cudaFuncAttributeMaxDynamicSharedMemorySize, SMEM_BYTES);
        smem_set = 1;
    }

    prep_kernel<<<(DD * DD + 255) / 256, 256>>>(W);
    score_kernel<<<NN / MT, 512, SMEM_BYTES>>>(xs, bias, attn);
    weights_kernel<<<BB, 256>>>(mask);
    stats_kernel<<<dim3(BB, 8), 256>>>(xs);
    finalize_kernel<<<BB, 256>>>(out);
}